// round 9
// baseline (speedup 1.0000x reference)
#include <cuda_runtime.h>
#include <cuda_bf16.h>
#include <cstdint>

// ===========================================================================
// ps_component: conv3x3(128->128)+relu+tidy fused via mma.sync (bf16 hi/lo
// 3-pass, fp32 acc). R8: software-pipelined cp.async mainloop (A+B double
// buffered, wait_group 1), higher-occupancy p5 path.
// ===========================================================================

#define SWZ(o) ((o) ^ (((o) >> 3) & 0x70))

__device__ __forceinline__ uint32_t smem_to_u32(const void* p) {
    uint32_t a;
    asm("{ .reg .u64 t; cvta.to.shared.u64 t, %1; cvt.u32.u64 %0, t; }"
        : "=r"(a) : "l"(p));
    return a;
}
__device__ __forceinline__ void ldsm_x4(uint32_t& r0, uint32_t& r1, uint32_t& r2,
                                        uint32_t& r3, uint32_t addr) {
    asm volatile("ldmatrix.sync.aligned.m8n8.x4.shared.b16 {%0,%1,%2,%3}, [%4];"
                 : "=r"(r0), "=r"(r1), "=r"(r2), "=r"(r3) : "r"(addr));
}
__device__ __forceinline__ void mma16816(float* d, const uint32_t* a, const uint32_t* b) {
    asm volatile(
        "mma.sync.aligned.m16n8k16.row.col.f32.bf16.bf16.f32 "
        "{%0,%1,%2,%3}, {%4,%5,%6,%7}, {%8,%9}, {%0,%1,%2,%3};"
        : "+f"(d[0]), "+f"(d[1]), "+f"(d[2]), "+f"(d[3])
        : "r"(a[0]), "r"(a[1]), "r"(a[2]), "r"(a[3]), "r"(b[0]), "r"(b[1]));
}
__device__ __forceinline__ void cp_async16(uint32_t saddr, const void* g) {
    asm volatile("cp.async.cg.shared.global [%0], [%1], 16;" :: "r"(saddr), "l"(g));
}
__device__ __forceinline__ void cp_commit() {
    asm volatile("cp.async.commit_group;");
}
template <int N>
__device__ __forceinline__ void cp_wait() {
    asm volatile("cp.async.wait_group %0;" :: "n"(N));
}

// ---------------- global scratch ----------------
// transposed/split inputs [b][hp][jp][ci], 128 ci contiguous bf16
//   p2: Hp=66 Wp=136 off 0     p3: Hp=34 Wp=72 off 73531392
//   p4: Hp=18 Wp=40 off 93585408
__device__ __align__(128) __nv_bfloat16 g_Thi[99483648];
__device__ __align__(128) __nv_bfloat16 g_Tlo[99483648];
// weights [level][tap][co][ci]; level offsets 0/147456/294912
__device__ __align__(128) __nv_bfloat16 g_Ahi[442368];
__device__ __align__(128) __nv_bfloat16 g_Alo[442368];
// tidy partials: p2@0 [64][64][128], p3@524288 [64][32][64],
//                p4@655360 [64][16][32], p5@688128 [64][8][16]
__device__ float g_part[697344];

// ---------------- pre-pass: weight reorder + hi/lo split ----------------
__global__ void wsplit(const float* __restrict__ w, int lev_off) {
    int i = blockIdx.x * 256 + threadIdx.x;
    if (i >= 147456) return;
    int tap = i / 16384, r = i & 16383, co = r >> 7, ci = r & 127;
    float v = w[(co * 128 + ci) * 9 + tap];
    __nv_bfloat16 h = __float2bfloat16(v);
    g_Ahi[lev_off + i] = h;
    g_Alo[lev_off + i] = __float2bfloat16(v - __bfloat162float(h));
}

// ---------------- pre-pass: input transpose + hi/lo split ----------------
__global__ void transpose_split(const float* __restrict__ x, int H, int W, int Wp,
                                size_t toff) {
    extern __shared__ float s[];   // [64][W+1]
    const int h = blockIdx.x, half = blockIdx.y, b = blockIdx.z;
    const int tid = threadIdx.x;
    const int pitch = W + 1;
    const float* xb = x + (((size_t)b * 128 + half * 64) * H + h) * W;
    const int nq = 64 * (W / 4);
    for (int i = tid; i < nq; i += 256) {
        int ci = i / (W / 4), wq = i % (W / 4);
        float4 v = *(const float4*)(xb + (size_t)ci * H * W + wq * 4);
        float* sp = s + ci * pitch + wq * 4;
        sp[0] = v.x; sp[1] = v.y; sp[2] = v.z; sp[3] = v.w;
    }
    __syncthreads();
    const int Hp = H + 2;
    size_t rowbase = toff + (((size_t)b * Hp + (h + 1)) * Wp) * 128 + half * 64;
    const int ntask = Wp * 8;
    for (int t = tid; t < ntask; t += 256) {
        int j = t >> 3, q = t & 7;
        uint4 hi4 = make_uint4(0, 0, 0, 0), lo4 = make_uint4(0, 0, 0, 0);
        if (j >= 1 && j <= W) {
            int w = j - 1;
            unsigned hr[4], lr[4];
#pragma unroll
            for (int e = 0; e < 4; e++) {
                float a = s[(q * 8 + 2 * e) * pitch + w];
                float c = s[(q * 8 + 2 * e + 1) * pitch + w];
                __nv_bfloat16 ah = __float2bfloat16(a);
                __nv_bfloat16 ch = __float2bfloat16(c);
                __nv_bfloat16 al = __float2bfloat16(a - __bfloat162float(ah));
                __nv_bfloat16 cl = __float2bfloat16(c - __bfloat162float(ch));
                hr[e] = (unsigned)__bfloat16_as_ushort(ah) | ((unsigned)__bfloat16_as_ushort(ch) << 16);
                lr[e] = (unsigned)__bfloat16_as_ushort(al) | ((unsigned)__bfloat16_as_ushort(cl) << 16);
            }
            hi4 = make_uint4(hr[0], hr[1], hr[2], hr[3]);
            lo4 = make_uint4(lr[0], lr[1], lr[2], lr[3]);
        }
        *(uint4*)(g_Thi + rowbase + (size_t)j * 128 + q * 8) = hi4;
        *(uint4*)(g_Tlo + rowbase + (size_t)j * 128 + q * 8) = lo4;
    }
}

__global__ void halo_zero(size_t toff, int Hp, int Wp) {
    int b = blockIdx.y;
    size_t base = toff + (((size_t)b * Hp + (blockIdx.x ? (Hp - 1) : 0)) * Wp) * 128;
    int n = Wp * 16;
    for (int t = threadIdx.x; t < n; t += 256) {
        *(uint4*)(g_Thi + base + (size_t)t * 8) = make_uint4(0, 0, 0, 0);
        *(uint4*)(g_Tlo + base + (size_t)t * 8) = make_uint4(0, 0, 0, 0);
    }
}

// ---------------- fused conv3x3 implicit GEMM via mma.sync ----------------
// 18 pipeline stages: s = (c0 half)*9 + dy*3 + dx. A (32KB: hi+lo for one
// tap) double-buffered per stage; B (2 planes of RB rows) double-buffered per
// (c0,dy) = s/3, prefetched 2 stages ahead. wait_group 1 -> one group in
// flight behind compute.
template <int W, int P, int H, int Wp>
__global__ void __launch_bounds__(256, 1) conv_mma(
    size_t toff, int aoff,
    const float* __restrict__ bs, const float* __restrict__ wt, int part_off) {
    constexpr int WJ = W + 2;
    constexpr int RB = P * WJ;
    constexpr int Hp = H + 2;
    constexpr int A_OFF = 0;                     // 2 x 32KB
    constexpr int B_OFF = 65536;
    constexpr int BSZ = 2 * RB * 128;            // hi+lo planes
    constexpr int RED = B_OFF + 2 * BSZ;

    extern __shared__ char smem[];
    const uint32_t su = smem_to_u32(smem);
    float* red = (float*)(smem + RED);
    const int tid = threadIdx.x, wid = tid >> 5, lane = tid & 31;
    const int mw = wid >> 2;
    const int nw = wid & 3;
    const int h0 = blockIdx.x * P;
    const int b = blockIdx.y;

    int arow[4];
#pragma unroll
    for (int mt = 0; mt < 4; mt++)
        arow[mt] = (mw * 64 + mt * 16 + (lane & 7) + ((lane >> 3) & 1) * 8) * 128
                   + (lane >> 4) * 16;
    int brow[4];
#pragma unroll
    for (int p = 0; p < 4; p++) {
        int g = lane >> 3;
        int nt = 2 * p + (g >> 1);
        int koff = (g & 1) * 16;
        int nn = nw * 64 + nt * 8 + (lane & 7);
        int v = nn / W, w = nn % W;
        brow[p] = (v * WJ + w) * 128 + koff;
    }

    // stage issue helpers
    auto issue_A = [&](int s) {
        int c0 = (s / 9) * 64;
        int rem = s % 9;
        int dy = rem / 3, dx = rem % 3;
        uint32_t dst0 = su + A_OFF + (s & 1) * 32768;
        for (int i = tid; i < 2048; i += 256) {
            int pl = i >= 1024;
            int r = i & 1023, co = r >> 3, q = r & 7;
            const __nv_bfloat16* src = (pl ? g_Alo : g_Ahi) + aoff +
                (((dy * 3 + dx) * 128 + co) * 128 + c0 + q * 8);
            cp_async16(dst0 + pl * 16384 + SWZ(co * 128 + q * 16), src);
        }
    };
    auto issue_B = [&](int t) {
        int c0 = (t / 3) * 64;
        int dy = t % 3;
        uint32_t dst0 = su + B_OFF + (t & 1) * BSZ;
        for (int i = tid; i < 2 * RB * 8; i += 256) {
            int pl = i >= RB * 8;
            int r8 = pl ? i - RB * 8 : i;
            int row = r8 >> 3, q = r8 & 7;
            int v = row / WJ, j = row - v * WJ;
            const __nv_bfloat16* src = (pl ? g_Tlo : g_Thi) + toff +
                (((size_t)b * Hp + (h0 + v + dy)) * Wp + j) * 128 + c0 + q * 8;
            cp_async16(dst0 + pl * (RB * 128) + SWZ(row * 128 + q * 16), src);
        }
    };

    float acc[4][8][4];
#pragma unroll
    for (int mt = 0; mt < 4; mt++)
#pragma unroll
        for (int nt = 0; nt < 8; nt++)
#pragma unroll
            for (int c = 0; c < 4; c++) acc[mt][nt][c] = 0.f;

    // prologue: G0 = B0 + A0, G1 = A1
    issue_B(0); issue_A(0); cp_commit();
    issue_A(1); cp_commit();

#pragma unroll 1
    for (int s = 0; s < 18; s++) {
        cp_wait<1>();          // group for stage s complete
        __syncthreads();       // cross-thread visibility

        const int dx = s % 3;
        const int t = s / 3;
        const uint32_t abh = su + A_OFF + (s & 1) * 32768;
        const uint32_t abl = abh + 16384;
        const uint32_t bhi = su + B_OFF + (t & 1) * BSZ;
        const uint32_t blo = bhi + RB * 128;
#pragma unroll
        for (int ks = 0; ks < 4; ks++) {
            uint32_t afh[4][4], afl[4][4], bfh[8][2], bfl[8][2];
#pragma unroll
            for (int mt = 0; mt < 4; mt++) {
                ldsm_x4(afh[mt][0], afh[mt][1], afh[mt][2], afh[mt][3],
                        abh + SWZ(arow[mt] + ks * 32));
                ldsm_x4(afl[mt][0], afl[mt][1], afl[mt][2], afl[mt][3],
                        abl + SWZ(arow[mt] + ks * 32));
            }
#pragma unroll
            for (int p = 0; p < 4; p++) {
                int off = SWZ(brow[p] + dx * 128 + ks * 32);
                ldsm_x4(bfh[2 * p][0], bfh[2 * p][1],
                        bfh[2 * p + 1][0], bfh[2 * p + 1][1], bhi + off);
                ldsm_x4(bfl[2 * p][0], bfl[2 * p][1],
                        bfl[2 * p + 1][0], bfl[2 * p + 1][1], blo + off);
            }
#pragma unroll
            for (int mt = 0; mt < 4; mt++)
#pragma unroll
                for (int nt = 0; nt < 8; nt++) {
                    mma16816(acc[mt][nt], afh[mt], bfh[nt]);
                    mma16816(acc[mt][nt], afh[mt], bfl[nt]);
                    mma16816(acc[mt][nt], afl[mt], bfh[nt]);
                }
        }
        __syncthreads();       // compute done before overwriting buffers
        int s2 = s + 2;
        if (s2 < 18) {
            if (s2 % 3 == 0) issue_B(s2 / 3);
            issue_A(s2);
        }
        cp_commit();           // uniform group accounting (empty at tail)
    }

    // ---- epilogue: relu + tidy reduce over co ----
    float p0[8], p1[8];
#pragma unroll
    for (int nt = 0; nt < 8; nt++) { p0[nt] = 0.f; p1[nt] = 0.f; }
#pragma unroll
    for (int mt = 0; mt < 4; mt++) {
        int r0 = mw * 64 + mt * 16 + (lane >> 2);
        float bb0 = bs[r0], ww0 = wt[r0];
        float bb1 = bs[r0 + 8], ww1 = wt[r0 + 8];
#pragma unroll
        for (int nt = 0; nt < 8; nt++) {
            p0[nt] += ww0 * fmaxf(acc[mt][nt][0] + bb0, 0.f)
                    + ww1 * fmaxf(acc[mt][nt][2] + bb1, 0.f);
            p1[nt] += ww0 * fmaxf(acc[mt][nt][1] + bb0, 0.f)
                    + ww1 * fmaxf(acc[mt][nt][3] + bb1, 0.f);
        }
    }
#pragma unroll
    for (int off = 4; off <= 16; off <<= 1)
#pragma unroll
        for (int nt = 0; nt < 8; nt++) {
            p0[nt] += __shfl_xor_sync(0xffffffffu, p0[nt], off);
            p1[nt] += __shfl_xor_sync(0xffffffffu, p1[nt], off);
        }
    if (lane < 4) {
#pragma unroll
        for (int nt = 0; nt < 8; nt++) {
            red[mw * 256 + nw * 64 + nt * 8 + 2 * lane]     = p0[nt];
            red[mw * 256 + nw * 64 + nt * 8 + 2 * lane + 1] = p1[nt];
        }
    }
    __syncthreads();
    {
        int n = tid;
        int v = n / W, w = n % W;
        g_part[part_off + ((size_t)b * H + (h0 + v)) * W + w] = red[n] + red[256 + n];
    }
}

// ---------------- p5 linear path (2-stage deterministic) ----------------
__global__ void __launch_bounds__(256) p5_reduce(
    const float* __restrict__ p5, const float* __restrict__ wt,
    const float* __restrict__ wpl) {
    const int b = blockIdx.x, grp = blockIdx.y, tid = threadIdx.x;
    const int x = tid & 15, sg = tid >> 4;
    float wph[8];
#pragma unroll
    for (int hh = 0; hh < 8; ++hh) wph[hh] = wpl[hh];
    float s = 0.f;
#pragma unroll
    for (int it = 0; it < 4; it++) {
        int ci = grp * 64 + sg + it * 16;
        float wtc = wt[ci];
        const float* pp = p5 + (((size_t)b * 512 + ci) * 8) * 16 + x;
#pragma unroll
        for (int hh = 0; hh < 8; ++hh) s = fmaf(wtc * wph[hh], pp[hh * 16], s);
    }
    __shared__ float red[256];
    red[tid] = s;
    __syncthreads();
    if (sg == 0) {
        float t = 0.f;
#pragma unroll
        for (int gg = 0; gg < 16; ++gg) t += red[gg * 16 + x];
        g_part[688128 + (b * 8 + grp) * 16 + x] = t;
    }
}

// ---------------- finalize ----------------
__global__ void finalize(
    const float* __restrict__ wpl1, const float* __restrict__ wpl2,
    const float* __restrict__ wpl3, const float* __restrict__ wpl4,
    const float* __restrict__ bt1, const float* __restrict__ bpl1,
    const float* __restrict__ bt2, const float* __restrict__ bpl2,
    const float* __restrict__ bt3, const float* __restrict__ bpl3,
    const float* __restrict__ bt4, const float* __restrict__ bpl4,
    float* __restrict__ out) {
    int idx = blockIdx.x * blockDim.x + threadIdx.x;
    if (idx >= 64 * 240) return;
    int b = idx / 240, col = idx % 240;
    float s = 0.f, sw = 0.f;
    if (col < 128) {
        int w = col;
        for (int hh = 0; hh < 64; ++hh) {
            float wp = wpl1[hh]; sw += wp;
            s = fmaf(wp, g_part[((size_t)b * 64 + hh) * 128 + w], s);
        }
        s += bt1[0] * sw + bpl1[0];
    } else if (col < 192) {
        int w = col - 128;
        for (int hh = 0; hh < 32; ++hh) {
            float wp = wpl2[hh]; sw += wp;
            s = fmaf(wp, g_part[524288 + ((size_t)b * 32 + hh) * 64 + w], s);
        }
        s += bt2[0] * sw + bpl2[0];
    } else if (col < 224) {
        int w = col - 192;
        for (int hh = 0; hh < 16; ++hh) {
            float wp = wpl3[hh]; sw += wp;
            s = fmaf(wp, g_part[655360 + ((size_t)b * 16 + hh) * 32 + w], s);
        }
        s += bt3[0] * sw + bpl3[0];
    } else {
        int x = col - 224;
        for (int g = 0; g < 8; ++g) s += g_part[688128 + (b * 8 + g) * 16 + x];
        for (int hh = 0; hh < 8; ++hh) sw += wpl4[hh];
        s += bt4[0] * sw + bpl4[0];
    }
    out[idx] = s;
}

// ---------------- host ----------------
extern "C" void kernel_launch(void* const* d_in, const int* in_sizes, int n_in,
                              void* d_out, int out_size) {
    (void)in_sizes; (void)n_in; (void)out_size;
    const float* p2 = (const float*)d_in[0];
    const float* p3 = (const float*)d_in[1];
    const float* p4 = (const float*)d_in[2];
    const float* p5 = (const float*)d_in[3];
    const float* w_s1 = (const float*)d_in[4];  const float* b_s1 = (const float*)d_in[5];
    const float* w_s2 = (const float*)d_in[6];  const float* b_s2 = (const float*)d_in[7];
    const float* w_s3 = (const float*)d_in[8];  const float* b_s3 = (const float*)d_in[9];
    const float* w_t1 = (const float*)d_in[10]; const float* b_t1 = (const float*)d_in[11];
    const float* w_t2 = (const float*)d_in[12]; const float* b_t2 = (const float*)d_in[13];
    const float* w_t3 = (const float*)d_in[14]; const float* b_t3 = (const float*)d_in[15];
    const float* w_t4 = (const float*)d_in[16]; const float* b_t4 = (const float*)d_in[17];
    const float* w_pl1 = (const float*)d_in[18]; const float* b_pl1 = (const float*)d_in[19];
    const float* w_pl2 = (const float*)d_in[20]; const float* b_pl2 = (const float*)d_in[21];
    const float* w_pl3 = (const float*)d_in[22]; const float* b_pl3 = (const float*)d_in[23];
    const float* w_pl4 = (const float*)d_in[24]; const float* b_pl4 = (const float*)d_in[25];
    float* out = (float*)d_out;

    const size_t T2 = 0, T3 = 73531392, T4 = 93585408;
    // smem: A ring(64KB) + B ring(2*BSZ) + red(2KB)
    const int s2 = 65536 + 2 * (2 * 2 * 130 * 128) + 2048;   // 200704
    const int s3 = 65536 + 2 * (2 * 4 * 66 * 128) + 2048;    // 202752
    const int s4 = 65536 + 2 * (2 * 8 * 34 * 128) + 2048;    // 206848

    cudaFuncSetAttribute(transpose_split, cudaFuncAttributeMaxDynamicSharedMemorySize, 33024);
    cudaFuncSetAttribute(conv_mma<128, 2, 64, 136>, cudaFuncAttributeMaxDynamicSharedMemorySize, s2);
    cudaFuncSetAttribute(conv_mma<64, 4, 32, 72>,   cudaFuncAttributeMaxDynamicSharedMemorySize, s3);
    cudaFuncSetAttribute(conv_mma<32, 8, 16, 40>,   cudaFuncAttributeMaxDynamicSharedMemorySize, s4);

    wsplit<<<576, 256>>>(w_s1, 0);
    wsplit<<<576, 256>>>(w_s2, 147456);
    wsplit<<<576, 256>>>(w_s3, 294912);

    transpose_split<<<dim3(64, 2, 64), 256, 33024>>>(p2, 64, 128, 136, T2);
    transpose_split<<<dim3(32, 2, 64), 256, 16768>>>(p3, 32, 64, 72, T3);
    transpose_split<<<dim3(16, 2, 64), 256, 8576>>>(p4, 16, 32, 40, T4);
    halo_zero<<<dim3(2, 64), 256>>>(T2, 66, 136);
    halo_zero<<<dim3(2, 64), 256>>>(T3, 34, 72);
    halo_zero<<<dim3(2, 64), 256>>>(T4, 18, 40);

    conv_mma<128, 2, 64, 136><<<dim3(32, 64), 256, s2>>>(T2, 0,      b_s1, w_t1, 0);
    conv_mma<64, 4, 32, 72>  <<<dim3(8, 64),  256, s3>>>(T3, 147456, b_s2, w_t2, 524288);
    conv_mma<32, 8, 16, 40>  <<<dim3(2, 64),  256, s4>>>(T4, 294912, b_s3, w_t3, 655360);

    p5_reduce<<<dim3(64, 8), 256>>>(p5, w_t4, w_pl4);
    finalize<<<(64 * 240 + 255) / 256, 256>>>(w_pl1, w_pl2, w_pl3, w_pl4,
                                              b_t1, b_pl1, b_t2, b_pl2,
                                              b_t3, b_pl3, b_t4, b_pl4, out);
}

// round 10
// speedup vs baseline: 1.0833x; 1.0833x over previous
#include <cuda_runtime.h>
#include <cuda_bf16.h>
#include <cstdint>

// ===========================================================================
// ps_component: conv3x3(128->128)+relu+tidy fused via mma.sync (bf16 hi/lo
// 3-pass, fp32 acc). R9: R7 mainloop (proven fastest) + all three conv levels
// fused into ONE launch (tail-wave packing), fused pre-pass launches.
// ===========================================================================

#define SWZ(o) ((o) ^ (((o) >> 3) & 0x70))

__device__ __forceinline__ uint32_t smem_to_u32(const void* p) {
    uint32_t a;
    asm("{ .reg .u64 t; cvta.to.shared.u64 t, %1; cvt.u32.u64 %0, t; }"
        : "=r"(a) : "l"(p));
    return a;
}
__device__ __forceinline__ void ldsm_x4(uint32_t& r0, uint32_t& r1, uint32_t& r2,
                                        uint32_t& r3, uint32_t addr) {
    asm volatile("ldmatrix.sync.aligned.m8n8.x4.shared.b16 {%0,%1,%2,%3}, [%4];"
                 : "=r"(r0), "=r"(r1), "=r"(r2), "=r"(r3) : "r"(addr));
}
__device__ __forceinline__ void mma16816(float* d, const uint32_t* a, const uint32_t* b) {
    asm volatile(
        "mma.sync.aligned.m16n8k16.row.col.f32.bf16.bf16.f32 "
        "{%0,%1,%2,%3}, {%4,%5,%6,%7}, {%8,%9}, {%0,%1,%2,%3};"
        : "+f"(d[0]), "+f"(d[1]), "+f"(d[2]), "+f"(d[3])
        : "r"(a[0]), "r"(a[1]), "r"(a[2]), "r"(a[3]), "r"(b[0]), "r"(b[1]));
}
__device__ __forceinline__ void cp_async16(uint32_t saddr, const void* g) {
    asm volatile("cp.async.cg.shared.global [%0], [%1], 16;" :: "r"(saddr), "l"(g));
}
__device__ __forceinline__ void cp_async_wait_all() {
    asm volatile("cp.async.commit_group;");
    asm volatile("cp.async.wait_group 0;");
}

// ---------------- global scratch ----------------
// transposed/split inputs [b][hp][jp][ci], 128 ci contiguous bf16
//   p2: Hp=66 Wp=136 off 0     p3: Hp=34 Wp=72 off 73531392
//   p4: Hp=18 Wp=40 off 93585408
__device__ __align__(128) __nv_bfloat16 g_Thi[99483648];
__device__ __align__(128) __nv_bfloat16 g_Tlo[99483648];
// weights [level][tap][co][ci]; level offsets 0/147456/294912
__device__ __align__(128) __nv_bfloat16 g_Ahi[442368];
__device__ __align__(128) __nv_bfloat16 g_Alo[442368];
// tidy partials: p2@0 [64][64][128], p3@524288 [64][32][64],
//                p4@655360 [64][16][32], p5@688128 [64][8][16]
__device__ float g_part[697344];

// ---------------- pre-pass: weight reorder + hi/lo split (all levels) -----
__global__ void wsplit_all(const float* __restrict__ w1,
                           const float* __restrict__ w2,
                           const float* __restrict__ w3) {
    int gi = blockIdx.x * 256 + threadIdx.x;
    if (gi >= 3 * 147456) return;
    int lev = gi / 147456, i = gi % 147456;
    const float* w = lev == 0 ? w1 : (lev == 1 ? w2 : w3);
    int tap = i / 16384, r = i & 16383, co = r >> 7, ci = r & 127;
    float v = w[(co * 128 + ci) * 9 + tap];
    __nv_bfloat16 h = __float2bfloat16(v);
    g_Ahi[lev * 147456 + i] = h;
    g_Alo[lev * 147456 + i] = __float2bfloat16(v - __bfloat162float(h));
}

// ---------------- pre-pass: input transpose + hi/lo split ----------------
__global__ void transpose_split(const float* __restrict__ x, int H, int W, int Wp,
                                size_t toff) {
    extern __shared__ float s[];   // [64][W+1]
    const int h = blockIdx.x, half = blockIdx.y, b = blockIdx.z;
    const int tid = threadIdx.x;
    const int pitch = W + 1;
    const float* xb = x + (((size_t)b * 128 + half * 64) * H + h) * W;
    const int nq = 64 * (W / 4);
    for (int i = tid; i < nq; i += 256) {
        int ci = i / (W / 4), wq = i % (W / 4);
        float4 v = *(const float4*)(xb + (size_t)ci * H * W + wq * 4);
        float* sp = s + ci * pitch + wq * 4;
        sp[0] = v.x; sp[1] = v.y; sp[2] = v.z; sp[3] = v.w;
    }
    __syncthreads();
    const int Hp = H + 2;
    size_t rowbase = toff + (((size_t)b * Hp + (h + 1)) * Wp) * 128 + half * 64;
    const int ntask = Wp * 8;
    for (int t = tid; t < ntask; t += 256) {
        int j = t >> 3, q = t & 7;
        uint4 hi4 = make_uint4(0, 0, 0, 0), lo4 = make_uint4(0, 0, 0, 0);
        if (j >= 1 && j <= W) {
            int w = j - 1;
            unsigned hr[4], lr[4];
#pragma unroll
            for (int e = 0; e < 4; e++) {
                float a = s[(q * 8 + 2 * e) * pitch + w];
                float c = s[(q * 8 + 2 * e + 1) * pitch + w];
                __nv_bfloat16 ah = __float2bfloat16(a);
                __nv_bfloat16 ch = __float2bfloat16(c);
                __nv_bfloat16 al = __float2bfloat16(a - __bfloat162float(ah));
                __nv_bfloat16 cl = __float2bfloat16(c - __bfloat162float(ch));
                hr[e] = (unsigned)__bfloat16_as_ushort(ah) | ((unsigned)__bfloat16_as_ushort(ch) << 16);
                lr[e] = (unsigned)__bfloat16_as_ushort(al) | ((unsigned)__bfloat16_as_ushort(cl) << 16);
            }
            hi4 = make_uint4(hr[0], hr[1], hr[2], hr[3]);
            lo4 = make_uint4(lr[0], lr[1], lr[2], lr[3]);
        }
        *(uint4*)(g_Thi + rowbase + (size_t)j * 128 + q * 8) = hi4;
        *(uint4*)(g_Tlo + rowbase + (size_t)j * 128 + q * 8) = lo4;
    }
}

// all halo rows (top+bottom, all levels) in one launch
__global__ void halo_zero_all() {
    // tasks: lev0: 2*64 rows of 136*16, lev1: 2*64 of 72*16, lev2: 2*64 of 40*16
    const int lev = blockIdx.x / 128;
    const int r = blockIdx.x % 128;       // (top/bot)*64 + b
    const int topbot = r >> 6, b = r & 63;
    const size_t toff = lev == 0 ? 0 : (lev == 1 ? 73531392 : 93585408);
    const int Hp = lev == 0 ? 66 : (lev == 1 ? 34 : 18);
    const int Wp = lev == 0 ? 136 : (lev == 1 ? 72 : 40);
    size_t base = toff + (((size_t)b * Hp + (topbot ? (Hp - 1) : 0)) * Wp) * 128;
    int n = Wp * 16;
    for (int t = threadIdx.x; t < n; t += 256) {
        *(uint4*)(g_Thi + base + (size_t)t * 8) = make_uint4(0, 0, 0, 0);
        *(uint4*)(g_Tlo + base + (size_t)t * 8) = make_uint4(0, 0, 0, 0);
    }
}

// ---------------- fused conv3x3 implicit GEMM via mma.sync ----------------
// R7 mainloop as a device function; one kernel dispatches all 3 levels.
template <int W, int P, int H, int Wp>
__device__ __forceinline__ void conv_body(
    char* smem, size_t toff, int aoff,
    const float* __restrict__ bs, const float* __restrict__ wt,
    int part_off, int hb, int b) {
    constexpr int WJ = W + 2;
    constexpr int RB = P * WJ;
    constexpr int Hp = H + 2;
    constexpr int A_OFF = 0;                 // 6 tiles [dx][pl] of 16KB
    constexpr int B_HI = 98304, B_LO = B_HI + RB * 128;
    constexpr int RED = B_HI + 2 * RB * 128;

    const uint32_t su = smem_to_u32(smem);
    float* red = (float*)(smem + RED);
    const int tid = threadIdx.x, wid = tid >> 5, lane = tid & 31;
    const int mw = wid >> 2;
    const int nw = wid & 3;
    const int h0 = hb * P;

    int arow[4];
#pragma unroll
    for (int mt = 0; mt < 4; mt++)
        arow[mt] = (mw * 64 + mt * 16 + (lane & 7) + ((lane >> 3) & 1) * 8) * 128
                   + (lane >> 4) * 16;
    int brow[4];
#pragma unroll
    for (int p = 0; p < 4; p++) {
        int g = lane >> 3;
        int nt = 2 * p + (g >> 1);
        int koff = (g & 1) * 16;
        int nn = nw * 64 + nt * 8 + (lane & 7);
        int v = nn / W, w = nn % W;
        brow[p] = (v * WJ + w) * 128 + koff;
    }

    float acc[4][8][4];
#pragma unroll
    for (int mt = 0; mt < 4; mt++)
#pragma unroll
        for (int nt = 0; nt < 8; nt++)
#pragma unroll
            for (int c = 0; c < 4; c++) acc[mt][nt][c] = 0.f;

    for (int c0 = 0; c0 < 128; c0 += 64) {
        for (int dy = 0; dy < 3; dy++) {
            __syncthreads();
            // ---- stage B (hi+lo) via cp.async
            for (int i = tid; i < 2 * RB * 8; i += 256) {
                int pl = i >= RB * 8;
                int r8 = pl ? i - RB * 8 : i;
                int row = r8 >> 3, q = r8 & 7;
                int v = row / WJ, j = row - v * WJ;
                const __nv_bfloat16* src = (pl ? g_Tlo : g_Thi) + toff +
                    (((size_t)b * Hp + (h0 + v + dy)) * Wp + j) * 128 + c0 + q * 8;
                cp_async16(su + (pl ? B_LO : B_HI) + SWZ(row * 128 + q * 16), src);
            }
            // ---- stage A (3 dx, hi+lo) via cp.async
            for (int i = tid; i < 6 * 1024; i += 256) {
                int t = i >> 10, r = i & 1023, co = r >> 3, q = r & 7;
                int dx = t >> 1, pl = t & 1;
                const __nv_bfloat16* src = (pl ? g_Alo : g_Ahi) + aoff +
                    (((dy * 3 + dx) * 128 + co) * 128 + c0 + q * 8);
                cp_async16(su + A_OFF + t * 16384 + SWZ(co * 128 + q * 16), src);
            }
            cp_async_wait_all();
            __syncthreads();

#pragma unroll
            for (int dx = 0; dx < 3; dx++) {
                const uint32_t abh = su + A_OFF + (dx * 2 + 0) * 16384;
                const uint32_t abl = su + A_OFF + (dx * 2 + 1) * 16384;
#pragma unroll
                for (int ks = 0; ks < 4; ks++) {
                    uint32_t afh[4][4], afl[4][4], bfh[8][2], bfl[8][2];
#pragma unroll
                    for (int mt = 0; mt < 4; mt++) {
                        ldsm_x4(afh[mt][0], afh[mt][1], afh[mt][2], afh[mt][3],
                                abh + SWZ(arow[mt] + ks * 32));
                        ldsm_x4(afl[mt][0], afl[mt][1], afl[mt][2], afl[mt][3],
                                abl + SWZ(arow[mt] + ks * 32));
                    }
#pragma unroll
                    for (int p = 0; p < 4; p++) {
                        int off = SWZ(brow[p] + dx * 128 + ks * 32);
                        ldsm_x4(bfh[2 * p][0], bfh[2 * p][1],
                                bfh[2 * p + 1][0], bfh[2 * p + 1][1], su + B_HI + off);
                        ldsm_x4(bfl[2 * p][0], bfl[2 * p][1],
                                bfl[2 * p + 1][0], bfl[2 * p + 1][1], su + B_LO + off);
                    }
#pragma unroll
                    for (int mt = 0; mt < 4; mt++)
#pragma unroll
                        for (int nt = 0; nt < 8; nt++) {
                            mma16816(acc[mt][nt], afh[mt], bfh[nt]);
                            mma16816(acc[mt][nt], afh[mt], bfl[nt]);
                            mma16816(acc[mt][nt], afl[mt], bfh[nt]);
                        }
                }
            }
        }
    }

    // ---- epilogue: relu + tidy reduce over co ----
    float p0[8], p1[8];
#pragma unroll
    for (int nt = 0; nt < 8; nt++) { p0[nt] = 0.f; p1[nt] = 0.f; }
#pragma unroll
    for (int mt = 0; mt < 4; mt++) {
        int r0 = mw * 64 + mt * 16 + (lane >> 2);
        float bb0 = bs[r0], ww0 = wt[r0];
        float bb1 = bs[r0 + 8], ww1 = wt[r0 + 8];
#pragma unroll
        for (int nt = 0; nt < 8; nt++) {
            p0[nt] += ww0 * fmaxf(acc[mt][nt][0] + bb0, 0.f)
                    + ww1 * fmaxf(acc[mt][nt][2] + bb1, 0.f);
            p1[nt] += ww0 * fmaxf(acc[mt][nt][1] + bb0, 0.f)
                    + ww1 * fmaxf(acc[mt][nt][3] + bb1, 0.f);
        }
    }
#pragma unroll
    for (int off = 4; off <= 16; off <<= 1)
#pragma unroll
        for (int nt = 0; nt < 8; nt++) {
            p0[nt] += __shfl_xor_sync(0xffffffffu, p0[nt], off);
            p1[nt] += __shfl_xor_sync(0xffffffffu, p1[nt], off);
        }
    if (lane < 4) {
#pragma unroll
        for (int nt = 0; nt < 8; nt++) {
            red[mw * 256 + nw * 64 + nt * 8 + 2 * lane]     = p0[nt];
            red[mw * 256 + nw * 64 + nt * 8 + 2 * lane + 1] = p1[nt];
        }
    }
    __syncthreads();
    {
        int n = tid;
        int v = n / W, w = n % W;
        g_part[part_off + ((size_t)b * H + (h0 + v)) * W + w] = red[n] + red[256 + n];
    }
}

// single launch covering p2 (2048 CTAs), p3 (512), p4 (128) -- p2 first so
// p3/p4 pack into p2's tail wave.
__global__ void __launch_bounds__(256, 1) conv_all(
    const float* __restrict__ b_s1, const float* __restrict__ w_t1,
    const float* __restrict__ b_s2, const float* __restrict__ w_t2,
    const float* __restrict__ b_s3, const float* __restrict__ w_t3) {
    extern __shared__ char smem[];
    int cid = blockIdx.x;
    if (cid < 2048) {
        conv_body<128, 2, 64, 136>(smem, 0, 0, b_s1, w_t1, 0, cid >> 6, cid & 63);
    } else if (cid < 2560) {
        int i = cid - 2048;
        conv_body<64, 4, 32, 72>(smem, 73531392, 147456, b_s2, w_t2, 524288,
                                 i >> 6, i & 63);
    } else {
        int i = cid - 2560;
        conv_body<32, 8, 16, 40>(smem, 93585408, 294912, b_s3, w_t3, 655360,
                                 i >> 6, i & 63);
    }
}

// ---------------- p5 linear path (2-stage deterministic) ----------------
__global__ void __launch_bounds__(256) p5_reduce(
    const float* __restrict__ p5, const float* __restrict__ wt,
    const float* __restrict__ wpl) {
    const int b = blockIdx.x, grp = blockIdx.y, tid = threadIdx.x;
    const int x = tid & 15, sg = tid >> 4;
    float wph[8];
#pragma unroll
    for (int hh = 0; hh < 8; ++hh) wph[hh] = wpl[hh];
    float s = 0.f;
#pragma unroll
    for (int it = 0; it < 4; it++) {
        int ci = grp * 64 + sg + it * 16;
        float wtc = wt[ci];
        const float* pp = p5 + (((size_t)b * 512 + ci) * 8) * 16 + x;
#pragma unroll
        for (int hh = 0; hh < 8; ++hh) s = fmaf(wtc * wph[hh], pp[hh * 16], s);
    }
    __shared__ float red[256];
    red[tid] = s;
    __syncthreads();
    if (sg == 0) {
        float t = 0.f;
#pragma unroll
        for (int gg = 0; gg < 16; ++gg) t += red[gg * 16 + x];
        g_part[688128 + (b * 8 + grp) * 16 + x] = t;
    }
}

// ---------------- finalize ----------------
__global__ void finalize(
    const float* __restrict__ wpl1, const float* __restrict__ wpl2,
    const float* __restrict__ wpl3, const float* __restrict__ wpl4,
    const float* __restrict__ bt1, const float* __restrict__ bpl1,
    const float* __restrict__ bt2, const float* __restrict__ bpl2,
    const float* __restrict__ bt3, const float* __restrict__ bpl3,
    const float* __restrict__ bt4, const float* __restrict__ bpl4,
    float* __restrict__ out) {
    int idx = blockIdx.x * blockDim.x + threadIdx.x;
    if (idx >= 64 * 240) return;
    int b = idx / 240, col = idx % 240;
    float s = 0.f, sw = 0.f;
    if (col < 128) {
        int w = col;
        for (int hh = 0; hh < 64; ++hh) {
            float wp = wpl1[hh]; sw += wp;
            s = fmaf(wp, g_part[((size_t)b * 64 + hh) * 128 + w], s);
        }
        s += bt1[0] * sw + bpl1[0];
    } else if (col < 192) {
        int w = col - 128;
        for (int hh = 0; hh < 32; ++hh) {
            float wp = wpl2[hh]; sw += wp;
            s = fmaf(wp, g_part[524288 + ((size_t)b * 32 + hh) * 64 + w], s);
        }
        s += bt2[0] * sw + bpl2[0];
    } else if (col < 224) {
        int w = col - 192;
        for (int hh = 0; hh < 16; ++hh) {
            float wp = wpl3[hh]; sw += wp;
            s = fmaf(wp, g_part[655360 + ((size_t)b * 16 + hh) * 32 + w], s);
        }
        s += bt3[0] * sw + bpl3[0];
    } else {
        int x = col - 224;
        for (int g = 0; g < 8; ++g) s += g_part[688128 + (b * 8 + g) * 16 + x];
        for (int hh = 0; hh < 8; ++hh) sw += wpl4[hh];
        s += bt4[0] * sw + bpl4[0];
    }
    out[idx] = s;
}

// ---------------- host ----------------
extern "C" void kernel_launch(void* const* d_in, const int* in_sizes, int n_in,
                              void* d_out, int out_size) {
    (void)in_sizes; (void)n_in; (void)out_size;
    const float* p2 = (const float*)d_in[0];
    const float* p3 = (const float*)d_in[1];
    const float* p4 = (const float*)d_in[2];
    const float* p5 = (const float*)d_in[3];
    const float* w_s1 = (const float*)d_in[4];  const float* b_s1 = (const float*)d_in[5];
    const float* w_s2 = (const float*)d_in[6];  const float* b_s2 = (const float*)d_in[7];
    const float* w_s3 = (const float*)d_in[8];  const float* b_s3 = (const float*)d_in[9];
    const float* w_t1 = (const float*)d_in[10]; const float* b_t1 = (const float*)d_in[11];
    const float* w_t2 = (const float*)d_in[12]; const float* b_t2 = (const float*)d_in[13];
    const float* w_t3 = (const float*)d_in[14]; const float* b_t3 = (const float*)d_in[15];
    const float* w_t4 = (const float*)d_in[16]; const float* b_t4 = (const float*)d_in[17];
    const float* w_pl1 = (const float*)d_in[18]; const float* b_pl1 = (const float*)d_in[19];
    const float* w_pl2 = (const float*)d_in[20]; const float* b_pl2 = (const float*)d_in[21];
    const float* w_pl3 = (const float*)d_in[22]; const float* b_pl3 = (const float*)d_in[23];
    const float* w_pl4 = (const float*)d_in[24]; const float* b_pl4 = (const float*)d_in[25];
    float* out = (float*)d_out;

    const size_t T2 = 0, T3 = 73531392, T4 = 93585408;
    // conv smem (max of levels): A 96KB + B 2*RB*128 + red 2KB
    const int sconv = 98304 + 2 * (8 * 34) * 128 + 2048;  // 169984 (p4 largest)

    cudaFuncSetAttribute(transpose_split, cudaFuncAttributeMaxDynamicSharedMemorySize, 33024);
    cudaFuncSetAttribute(conv_all, cudaFuncAttributeMaxDynamicSharedMemorySize, sconv);

    wsplit_all<<<(3 * 147456 + 255) / 256, 256>>>(w_s1, w_s2, w_s3);

    transpose_split<<<dim3(64, 2, 64), 256, 33024>>>(p2, 64, 128, 136, T2);
    transpose_split<<<dim3(32, 2, 64), 256, 16768>>>(p3, 32, 64, 72, T3);
    transpose_split<<<dim3(16, 2, 64), 256, 8576>>>(p4, 16, 32, 40, T4);
    halo_zero_all<<<384, 256>>>();

    conv_all<<<2688, 256, sconv>>>(b_s1, w_t1, b_s2, w_t2, b_s3, w_t3);

    p5_reduce<<<dim3(64, 8), 256>>>(p5, w_t4, w_pl4);
    finalize<<<(64 * 240 + 255) / 256, 256>>>(w_pl1, w_pl2, w_pl3, w_pl4,
                                              b_t1, b_pl1, b_t2, b_pl2,
                                              b_t3, b_pl3, b_t4, b_pl4, out);
}